// round 5
// baseline (speedup 1.0000x reference)
#include <cuda_runtime.h>
#include <math.h>

#define D 1024
#define D4 256          // D / 4
#define NROWS 50000
#define BPM 148         // blocks per module, main pass
#define KCHUNKS 64      // k-split chunks for vecmat
#define KROWS (D / KCHUNKS)

typedef unsigned long long u64;

// ---------------- scratch (device globals; no allocation allowed) -----------
__device__ float g_vm_partial[2][KCHUNKS][D]; // vecmat partials (reused twice)
__device__ float g_bw[2][D];                  // b_w per module
__device__ float g_main_partial[2][BPM][D];   // weighted-sum partials (UNnormalized)
__device__ float g_main_alpha[2][BPM];        // alpha-sum partials
__device__ float g_attn[2 * D];               // concat(res_in, res_out)

// packed f32x2 FMA: d = a*b + d   (SASS FFMA2; PTX-only form)
__device__ __forceinline__ void fma2(u64& d, u64 a, u64 b) {
    asm("fma.rn.f32x2 %0, %1, %2, %0;" : "+l"(d) : "l"(a), "l"(b));
}
__device__ __forceinline__ u64 pack2(float lo, float hi) {
    u64 r;
    asm("mov.b64 %0, {%1, %2};" : "=l"(r) : "f"(lo), "f"(hi));
    return r;
}
__device__ __forceinline__ void unpack2(float& lo, float& hi, u64 v) {
    asm("mov.b64 {%0, %1}, %2;" : "=f"(lo), "=f"(hi) : "l"(v));
}

// ---------------- stage-1 vecmat: b_w = b_alpha^T @ W_alpha ------------------
__global__ void vecmat_partial(const float* __restrict__ v0,
                               const float* __restrict__ M0,
                               const float* __restrict__ v1,
                               const float* __restrict__ M1) {
    int vec = blockIdx.y;
    const float* v = vec ? v1 : v0;
    const float4* M4 = (const float4*)(vec ? M1 : M0);
    int t = threadIdx.x;        // 0..255
    int k0 = blockIdx.x * KROWS;
    float4 acc = make_float4(0.f, 0.f, 0.f, 0.f);
#pragma unroll
    for (int kk = 0; kk < KROWS; kk++) {     // KROWS=16 fully unrolled -> MLP 16
        float vk = __ldg(v + k0 + kk);
        float4 m = M4[(size_t)(k0 + kk) * D4 + t];
        acc.x = fmaf(vk, m.x, acc.x);
        acc.y = fmaf(vk, m.y, acc.y);
        acc.z = fmaf(vk, m.z, acc.z);
        acc.w = fmaf(vk, m.w, acc.w);
    }
    ((float4*)g_vm_partial[vec][blockIdx.x])[t] = acc;
}

// ---------------- stage-2 vecmat fused with column reduce --------------------
// v[k] = sum_b g_main_partial[vec][b][k]  (computed in-block), then partial GEMV
__global__ void vecmat_so_partial(const float* __restrict__ M0,
                                  const float* __restrict__ M1) {
    int vec = blockIdx.y;
    const float4* M4 = (const float4*)(vec ? M1 : M0);
    int t = threadIdx.x;
    int k0 = blockIdx.x * KROWS;

    __shared__ float s_v[KROWS];

    // 16 groups of 16 threads; group g reduces column k0+g over BPM partials
    {
        int g = t >> 4, i = t & 15;
        float a = 0.f;
        for (int b = i; b < BPM; b += 16)
            a += g_main_partial[vec][b][k0 + g];
#pragma unroll
        for (int o = 8; o > 0; o >>= 1)
            a += __shfl_xor_sync(0xffffffffu, a, o);   // reduce within 16-lane half
        if (i == 0) s_v[g] = a;
    }
    __syncthreads();

    float4 acc = make_float4(0.f, 0.f, 0.f, 0.f);
#pragma unroll
    for (int kk = 0; kk < KROWS; kk++) {
        float vk = s_v[kk];
        float4 m = M4[(size_t)(k0 + kk) * D4 + t];
        acc.x = fmaf(vk, m.x, acc.x);
        acc.y = fmaf(vk, m.y, acc.y);
        acc.z = fmaf(vk, m.z, acc.z);
        acc.w = fmaf(vk, m.w, acc.w);
    }
    ((float4*)g_vm_partial[vec][blockIdx.x])[t] = acc;
}

// which==0 -> write g_bw; which==1 -> scale by 1/sum(alpha), write g_attn
__global__ void vecmat_reduce(int which) {
    int vec = blockIdx.x;
    int t = threadIdx.x;
    __shared__ float s_inv;

    if (which && t < 32) {    // deterministic fixed-order alpha total
        float a = 0.f;
        for (int b = t; b < BPM; b += 32) a += g_main_alpha[vec][b];
#pragma unroll
        for (int o = 16; o > 0; o >>= 1)
            a += __shfl_xor_sync(0xffffffffu, a, o);
        if (t == 0) s_inv = 1.0f / a;
    }

    float4 acc = make_float4(0.f, 0.f, 0.f, 0.f);
#pragma unroll 8
    for (int c = 0; c < KCHUNKS; c++) {
        float4 p = ((const float4*)g_vm_partial[vec][c])[t];
        acc.x += p.x; acc.y += p.y; acc.z += p.z; acc.w += p.w;
    }
    __syncthreads();
    if (which) {
        float inv = s_inv;
        acc.x *= inv; acc.y *= inv; acc.z *= inv; acc.w *= inv;
        ((float4*)&g_attn[vec * D])[t] = acc;
    } else {
        ((float4*)g_bw[vec])[t] = acc;
    }
}

// ---------------- main single-pass kernel (software-pipelined) ---------------
// warp-per-row: s = X_j . b_w ; alpha = exp(s) ; acc += alpha * X_j
// 2-deep row prefetch: next row's 8 LDG.128 issued before current row's math.
__global__ void __launch_bounds__(256, 2)
main_pass(const float* __restrict__ Xin, const float* __restrict__ Xout, int nrows) {
    int mod = blockIdx.y;
    const ulonglong2* X2 = (const ulonglong2*)(mod ? Xout : Xin); // 16B units, 256/row

    __shared__ float4 s_bw4[D4];
    __shared__ float4 s_red[8 * D4];
    __shared__ float  s_alpha[8];

    int t = threadIdx.x, warp = t >> 5, lane = t & 31;
    s_bw4[t] = ((const float4*)g_bw[mod])[t];
    __syncthreads();
    const ulonglong2* bw2 = (const ulonglong2*)s_bw4;

    u64 acc[16];
#pragma unroll
    for (int i = 0; i < 16; i++) acc[i] = 0ull;
    float asum = 0.f;

    const int NW = BPM * 8;
    int gw = blockIdx.x * 8 + warp;

    u64 rA[16], rB[16];

#define LOADROW(buf, row_)                                            \
    {                                                                 \
        const ulonglong2* xr = X2 + (size_t)(row_) * 256;             \
        _Pragma("unroll")                                             \
        for (int i = 0; i < 8; i++) {                                 \
            ulonglong2 v = xr[lane + 32 * i];                         \
            buf[2 * i] = v.x; buf[2 * i + 1] = v.y;                   \
        }                                                             \
    }

#define PROCESS(buf)                                                  \
    {                                                                 \
        u64 d0 = 0ull, d1 = 0ull;                                     \
        _Pragma("unroll")                                             \
        for (int i = 0; i < 8; i++) {                                 \
            ulonglong2 b = bw2[lane + 32 * i];                        \
            fma2(d0, buf[2 * i],     b.x);                            \
            fma2(d1, buf[2 * i + 1], b.y);                            \
        }                                                             \
        float a0, a1, b0, b1;                                         \
        unpack2(a0, a1, d0);                                          \
        unpack2(b0, b1, d1);                                          \
        float s = (a0 + a1) + (b0 + b1);                              \
        _Pragma("unroll")                                             \
        for (int o = 16; o > 0; o >>= 1)                              \
            s += __shfl_xor_sync(0xffffffffu, s, o);                  \
        float alpha = __expf(s);      /* lane-uniform */              \
        asum += alpha;                /* == warp total */             \
        u64 alpha2 = pack2(alpha, alpha);                             \
        _Pragma("unroll")                                             \
        for (int i = 0; i < 16; i++) fma2(acc[i], alpha2, buf[i]);    \
    }

    if (gw < nrows) {
        int row = gw;
        LOADROW(rA, row)
        while (true) {
            int rowB = row + NW;
            if (rowB < nrows) LOADROW(rB, rowB)
            PROCESS(rA)
            if (rowB >= nrows) break;
            int rowC = rowB + NW;
            if (rowC < nrows) LOADROW(rA, rowC)
            PROCESS(rB)
            if (rowC >= nrows) break;
            row = rowC;
        }
    }
#undef LOADROW
#undef PROCESS

    // deterministic block reduce: warp -> smem slot, fixed-order sum
#pragma unroll
    for (int i = 0; i < 8; i++) {
        float x, y, z, w;
        unpack2(x, y, acc[2 * i]);
        unpack2(z, w, acc[2 * i + 1]);
        s_red[warp * D4 + lane + 32 * i] = make_float4(x, y, z, w);
    }
    if (lane == 0) s_alpha[warp] = asum;
    __syncthreads();

    float4 tot = make_float4(0.f, 0.f, 0.f, 0.f);
#pragma unroll
    for (int w = 0; w < 8; w++) {
        float4 v = s_red[w * D4 + t];
        tot.x += v.x; tot.y += v.y; tot.z += v.z; tot.w += v.w;
    }
    ((float4*)g_main_partial[mod][blockIdx.x])[t] = tot;
    if (t == 0) {
        float a = 0.f;
#pragma unroll
        for (int w = 0; w < 8; w++) a += s_alpha[w];
        g_main_alpha[mod][blockIdx.x] = a;
    }
}

// ---------------- final: out[i] = elu( lin_W[i,:] . attn + lin_b[i] ) -------
__global__ void final_kernel(const float* __restrict__ linW,
                             const float* __restrict__ linb,
                             float* __restrict__ out) {
    __shared__ float4 sa[2 * D4];        // 2048 floats of attn
    __shared__ float  sw[8];
    int t = threadIdx.x;
    sa[t]        = ((const float4*)g_attn)[t];
    sa[t + D4]   = ((const float4*)g_attn)[t + D4];
    __syncthreads();

    int i = blockIdx.x;
    const float4* row = (const float4*)linW + (size_t)i * (2 * D4);
    float4 w1 = row[t],        a1 = sa[t];
    float4 w2 = row[t + D4],   a2 = sa[t + D4];
    float s = 0.f;
    s = fmaf(w1.x, a1.x, s); s = fmaf(w1.y, a1.y, s);
    s = fmaf(w1.z, a1.z, s); s = fmaf(w1.w, a1.w, s);
    s = fmaf(w2.x, a2.x, s); s = fmaf(w2.y, a2.y, s);
    s = fmaf(w2.z, a2.z, s); s = fmaf(w2.w, a2.w, s);

#pragma unroll
    for (int o = 16; o > 0; o >>= 1)
        s += __shfl_xor_sync(0xffffffffu, s, o);
    int warp = t >> 5, lane = t & 31;
    if (lane == 0) sw[warp] = s;
    __syncthreads();
    if (t == 0) {
        float tot = 0.f;
#pragma unroll
        for (int w = 0; w < 8; w++) tot += sw[w];
        tot += linb[i];
        out[i] = tot > 0.f ? tot : expm1f(tot);   // jax.nn.elu, alpha=1
    }
}

// ---------------- launcher ---------------------------------------------------
extern "C" void kernel_launch(void* const* d_in, const int* in_sizes, int n_in,
                              void* d_out, int out_size) {
    const float* X_in      = (const float*)d_in[0];
    const float* X_out     = (const float*)d_in[1];
    const float* W_alpha_i = (const float*)d_in[2];
    // d_in[3] = a_alpha_in : unused (constant cancels in normalization)
    const float* b_alpha_i = (const float*)d_in[4];
    const float* W_sum_i   = (const float*)d_in[5];
    const float* W_alpha_o = (const float*)d_in[6];
    // d_in[7] = a_alpha_out : unused
    const float* b_alpha_o = (const float*)d_in[8];
    const float* W_sum_o   = (const float*)d_in[9];
    const float* lin_W     = (const float*)d_in[10];
    const float* lin_b     = (const float*)d_in[11];
    float* out = (float*)d_out;

    int nrows = in_sizes[0] / D;   // 50000

    // 1) b_w = b_alpha^T @ W_alpha (both modules)
    vecmat_partial<<<dim3(KCHUNKS, 2), 256>>>(b_alpha_i, W_alpha_i,
                                              b_alpha_o, W_alpha_o);
    vecmat_reduce<<<2, 256>>>(0);

    // 2) single pass over X: alpha + unnormalized weighted sum (both modules)
    main_pass<<<dim3(BPM, 2), 256>>>(X_in, X_out, nrows);

    // 3) fused: column-reduce partials in-block, then partial GEMV vs W_sum
    vecmat_so_partial<<<dim3(KCHUNKS, 2), 256>>>(W_sum_i, W_sum_o);

    // 4) reduce + scale by 1/sum(alpha) -> g_attn
    vecmat_reduce<<<2, 256>>>(1);

    // 5) out = elu(attn @ lin_W^T + lin_b)
    final_kernel<<<D, 256>>>(lin_W, lin_b, out);
}

// round 6
// speedup vs baseline: 1.2789x; 1.2789x over previous
#include <cuda_runtime.h>
#include <math.h>

#define D 1024
#define D4 256          // D / 4
#define NROWS 50000
#define BPM 148         // blocks per module, main pass
#define KCHUNKS 64      // k-split chunks for vecmat
#define KROWS (D / KCHUNKS)

typedef unsigned long long u64;

// ---------------- scratch (device globals; no allocation allowed) -----------
__device__ float g_vm_partial[2][KCHUNKS][D]; // vecmat partials (reused twice)
__device__ float g_bw[2][D];                  // b_w per module
__device__ float g_main_partial[2][BPM][D];   // weighted-sum partials (UNnormalized)
__device__ float g_main_alpha[2][BPM];        // alpha-sum partials
__device__ float g_attn[2 * D];               // concat(res_in, res_out)

// packed f32x2 FMA: d = a*b + d   (SASS FFMA2; PTX-only form)
__device__ __forceinline__ void fma2(u64& d, u64 a, u64 b) {
    asm("fma.rn.f32x2 %0, %1, %2, %0;" : "+l"(d) : "l"(a), "l"(b));
}
__device__ __forceinline__ u64 pack2(float lo, float hi) {
    u64 r;
    asm("mov.b64 %0, {%1, %2};" : "=l"(r) : "f"(lo), "f"(hi));
    return r;
}
__device__ __forceinline__ void unpack2(float& lo, float& hi, u64 v) {
    asm("mov.b64 {%0, %1}, %2;" : "=f"(lo), "=f"(hi) : "l"(v));
}
// streaming 16B load (LDG.E.CS.128) — X has zero reuse
__device__ __forceinline__ void ldcs128(u64& a, u64& b, const void* p) {
    asm("ld.global.cs.v2.u64 {%0, %1}, [%2];" : "=l"(a), "=l"(b) : "l"(p));
}

// ---------------- tiny init (exists so main_pass is launch #4 for ncu) ------
__global__ void init_kernel() {
    ((float4*)g_attn)[threadIdx.x] = make_float4(0.f, 0.f, 0.f, 0.f);
    ((float4*)g_attn)[threadIdx.x + D4] = make_float4(0.f, 0.f, 0.f, 0.f);
}

// ---------------- stage-1 vecmat: b_w = b_alpha^T @ W_alpha ------------------
__global__ void vecmat_partial(const float* __restrict__ v0,
                               const float* __restrict__ M0,
                               const float* __restrict__ v1,
                               const float* __restrict__ M1) {
    int vec = blockIdx.y;
    const float* v = vec ? v1 : v0;
    const float4* M4 = (const float4*)(vec ? M1 : M0);
    int t = threadIdx.x;        // 0..255
    int k0 = blockIdx.x * KROWS;
    float4 acc = make_float4(0.f, 0.f, 0.f, 0.f);
#pragma unroll
    for (int kk = 0; kk < KROWS; kk++) {     // KROWS=16 fully unrolled -> MLP 16
        float vk = __ldg(v + k0 + kk);
        float4 m = M4[(size_t)(k0 + kk) * D4 + t];
        acc.x = fmaf(vk, m.x, acc.x);
        acc.y = fmaf(vk, m.y, acc.y);
        acc.z = fmaf(vk, m.z, acc.z);
        acc.w = fmaf(vk, m.w, acc.w);
    }
    ((float4*)g_vm_partial[vec][blockIdx.x])[t] = acc;
}

// ---------------- reduce vm partials, split across 8 blocks/module ----------
// which==0 -> g_bw ; which==1 -> scale by 1/sum(alpha) -> g_attn
__global__ void vecmat_reduce(int which) {
    int vec = blockIdx.y;
    int t = threadIdx.x, grp = t >> 5, lane = t & 31;
    int c4 = blockIdx.x * 32 + lane;              // float4 column

    __shared__ float4 s_m[8][32];
    __shared__ float  s_inv;

    if (which && t < 32) {     // deterministic fixed-order alpha total
        float a = 0.f;
        for (int b = t; b < BPM; b += 32) a += g_main_alpha[vec][b];
#pragma unroll
        for (int o = 16; o > 0; o >>= 1)
            a += __shfl_xor_sync(0xffffffffu, a, o);
        if (t == 0) s_inv = 1.0f / a;
    }

    float4 acc = make_float4(0.f, 0.f, 0.f, 0.f);
#pragma unroll
    for (int c = grp; c < KCHUNKS; c += 8) {      // 8 chunks per thread
        float4 p = ((const float4*)g_vm_partial[vec][c])[c4];
        acc.x += p.x; acc.y += p.y; acc.z += p.z; acc.w += p.w;
    }
    s_m[grp][lane] = acc;
    __syncthreads();
    if (grp == 0) {
        float4 tot = s_m[0][lane];
#pragma unroll
        for (int w = 1; w < 8; w++) {
            float4 v = s_m[w][lane];
            tot.x += v.x; tot.y += v.y; tot.z += v.z; tot.w += v.w;
        }
        if (which) {
            float inv = s_inv;
            tot.x *= inv; tot.y *= inv; tot.z *= inv; tot.w *= inv;
            ((float4*)&g_attn[vec * D])[c4] = tot;
        } else {
            ((float4*)g_bw[vec])[c4] = tot;
        }
    }
}

// ---------------- main single-pass kernel ------------------------------------
// warp-per-row: s = X_j . b_w ; alpha = exp(s) ; acc += alpha * X_j
// R4 structure (best measured): b_w in registers, no pipelining, + streaming loads
__global__ void __launch_bounds__(256, 2)
main_pass(const float* __restrict__ Xin, const float* __restrict__ Xout, int nrows) {
    int mod = blockIdx.y;
    const ulonglong2* X2 = (const ulonglong2*)(mod ? Xout : Xin); // 16B units, 256/row

    __shared__ float4 s_red[8 * D4];
    __shared__ float  s_alpha[8];

    int t = threadIdx.x, warp = t >> 5, lane = t & 31;

    // b_w slice for this lane: float4 columns lane+32*i, i=0..7 -> 16 u64
    u64 bw[16];
    {
        const ulonglong2* B2 = (const ulonglong2*)g_bw[mod];
#pragma unroll
        for (int i = 0; i < 8; i++) {
            ulonglong2 v = B2[lane + 32 * i];
            bw[2 * i] = v.x; bw[2 * i + 1] = v.y;
        }
    }

    u64 acc[16];
#pragma unroll
    for (int i = 0; i < 16; i++) acc[i] = 0ull;
    float asum = 0.f;

    int gw = blockIdx.x * 8 + warp;
    const int NW = BPM * 8;

    for (int row = gw; row < nrows; row += NW) {
        const ulonglong2* xr = X2 + (size_t)row * 256;
        u64 r[16];
#pragma unroll
        for (int i = 0; i < 8; i++)               // 8 LDG.E.CS.128 front-batched
            ldcs128(r[2 * i], r[2 * i + 1], xr + lane + 32 * i);

        // dot: two independent f32x2 chains for ILP
        u64 d0 = 0ull, d1 = 0ull;
#pragma unroll
        for (int i = 0; i < 8; i++) {
            fma2(d0, r[2 * i],     bw[2 * i]);
            fma2(d1, r[2 * i + 1], bw[2 * i + 1]);
        }
        float a0, a1, b0, b1;
        unpack2(a0, a1, d0);
        unpack2(b0, b1, d1);
        float s = (a0 + a1) + (b0 + b1);
#pragma unroll
        for (int o = 16; o > 0; o >>= 1)
            s += __shfl_xor_sync(0xffffffffu, s, o);

        float alpha = __expf(s);                  // lane-uniform after butterfly
        asum += alpha;                            // per-lane asum == warp total
        u64 alpha2 = pack2(alpha, alpha);
#pragma unroll
        for (int i = 0; i < 16; i++) fma2(acc[i], alpha2, r[i]);
    }

    // deterministic block reduce: warp -> smem slot, fixed-order sum
#pragma unroll
    for (int i = 0; i < 8; i++) {
        float x, y, z, w;
        unpack2(x, y, acc[2 * i]);
        unpack2(z, w, acc[2 * i + 1]);
        s_red[warp * D4 + lane + 32 * i] = make_float4(x, y, z, w);
    }
    if (lane == 0) s_alpha[warp] = asum;          // asum already warp-total
    __syncthreads();

    float4 tot = make_float4(0.f, 0.f, 0.f, 0.f);
#pragma unroll
    for (int w = 0; w < 8; w++) {
        float4 v = s_red[w * D4 + t];
        tot.x += v.x; tot.y += v.y; tot.z += v.z; tot.w += v.w;
    }
    ((float4*)g_main_partial[mod][blockIdx.x])[t] = tot;
    if (t == 0) {
        float a = 0.f;
#pragma unroll
        for (int w = 0; w < 8; w++) a += s_alpha[w];
        g_main_alpha[mod][blockIdx.x] = a;
    }
}

// ---------------- stage-2 vecmat fused with COALESCED column reduce ---------
// v[k0+g] = sum_b g_main_partial[vec][b][k0+g], then partial GEMV vs W_sum
__global__ void vecmat_so_partial(const float* __restrict__ M0,
                                  const float* __restrict__ M1) {
    int vec = blockIdx.y;
    const float4* M4 = (const float4*)(vec ? M1 : M0);
    int t = threadIdx.x;
    int k0 = blockIdx.x * KROWS;

    __shared__ float s_t[16][17];   // [rowgrp][col], padded
    __shared__ float s_v[KROWS];

    // COALESCED: consecutive threads -> consecutive columns within one row.
    // thread t: col g = t&15, rowgrp i = t>>4; reads rows i, i+16, ... (~9 loads)
    {
        int g = t & 15, i = t >> 4;
        float a = 0.f;
        for (int b = i; b < BPM; b += 16)
            a += g_main_partial[vec][b][k0 + g];
        s_t[i][g] = a;
    }
    __syncthreads();
    if (t < KROWS) {                // 16 threads finish the 16-way sums
        float a = 0.f;
#pragma unroll
        for (int i = 0; i < 16; i++) a += s_t[i][t];
        s_v[t] = a;
    }
    __syncthreads();

    float4 acc = make_float4(0.f, 0.f, 0.f, 0.f);
#pragma unroll
    for (int kk = 0; kk < KROWS; kk++) {
        float vk = s_v[kk];
        float4 m = M4[(size_t)(k0 + kk) * D4 + t];
        acc.x = fmaf(vk, m.x, acc.x);
        acc.y = fmaf(vk, m.y, acc.y);
        acc.z = fmaf(vk, m.z, acc.z);
        acc.w = fmaf(vk, m.w, acc.w);
    }
    ((float4*)g_vm_partial[vec][blockIdx.x])[t] = acc;
}

// ---------------- final: out[i] = elu( lin_W[i,:] . attn + lin_b[i] ) -------
__global__ void final_kernel(const float* __restrict__ linW,
                             const float* __restrict__ linb,
                             float* __restrict__ out) {
    __shared__ float4 sa[2 * D4];        // 2048 floats of attn
    __shared__ float  sw[8];
    int t = threadIdx.x;
    sa[t]        = ((const float4*)g_attn)[t];
    sa[t + D4]   = ((const float4*)g_attn)[t + D4];
    __syncthreads();

    int i = blockIdx.x;
    const float4* row = (const float4*)linW + (size_t)i * (2 * D4);
    float4 w1 = row[t],        a1 = sa[t];
    float4 w2 = row[t + D4],   a2 = sa[t + D4];
    float s = 0.f;
    s = fmaf(w1.x, a1.x, s); s = fmaf(w1.y, a1.y, s);
    s = fmaf(w1.z, a1.z, s); s = fmaf(w1.w, a1.w, s);
    s = fmaf(w2.x, a2.x, s); s = fmaf(w2.y, a2.y, s);
    s = fmaf(w2.z, a2.z, s); s = fmaf(w2.w, a2.w, s);

#pragma unroll
    for (int o = 16; o > 0; o >>= 1)
        s += __shfl_xor_sync(0xffffffffu, s, o);
    int warp = t >> 5, lane = t & 31;
    if (lane == 0) sw[warp] = s;
    __syncthreads();
    if (t == 0) {
        float tot = 0.f;
#pragma unroll
        for (int w = 0; w < 8; w++) tot += sw[w];
        tot += linb[i];
        out[i] = tot > 0.f ? tot : expm1f(tot);   // jax.nn.elu, alpha=1
    }
}

// ---------------- launcher ---------------------------------------------------
extern "C" void kernel_launch(void* const* d_in, const int* in_sizes, int n_in,
                              void* d_out, int out_size) {
    const float* X_in      = (const float*)d_in[0];
    const float* X_out     = (const float*)d_in[1];
    const float* W_alpha_i = (const float*)d_in[2];
    // d_in[3] = a_alpha_in : unused (constant cancels in normalization)
    const float* b_alpha_i = (const float*)d_in[4];
    const float* W_sum_i   = (const float*)d_in[5];
    const float* W_alpha_o = (const float*)d_in[6];
    // d_in[7] = a_alpha_out : unused
    const float* b_alpha_o = (const float*)d_in[8];
    const float* W_sum_o   = (const float*)d_in[9];
    const float* lin_W     = (const float*)d_in[10];
    const float* lin_b     = (const float*)d_in[11];
    float* out = (float*)d_out;

    int nrows = in_sizes[0] / D;   // 50000

    // #1: trivial init (also positions main_pass as launch #4 for ncu)
    init_kernel<<<1, 256>>>();

    // #2: b_w partials
    vecmat_partial<<<dim3(KCHUNKS, 2), 256>>>(b_alpha_i, W_alpha_i,
                                              b_alpha_o, W_alpha_o);
    // #3: reduce -> g_bw
    vecmat_reduce<<<dim3(8, 2), 256>>>(0);

    // #4: single pass over X (profiled launch)
    main_pass<<<dim3(BPM, 2), 256>>>(X_in, X_out, nrows);

    // #5: fused coalesced column-reduce + partial GEMV vs W_sum
    vecmat_so_partial<<<dim3(KCHUNKS, 2), 256>>>(W_sum_i, W_sum_o);

    // #6: reduce + scale by 1/sum(alpha) -> g_attn
    vecmat_reduce<<<dim3(8, 2), 256>>>(1);

    // #7: out = elu(attn @ lin_W^T + lin_b)
    final_kernel<<<D, 256>>>(lin_W, lin_b, out);
}

// round 7
// speedup vs baseline: 1.3205x; 1.0325x over previous
#include <cuda_runtime.h>
#include <math.h>

#define D 1024
#define D4 256          // D / 4
#define NROWS 50000
#define BPM 148         // blocks per module, main pass
#define KCHUNKS 64      // k-split chunks for vecmat
#define KROWS (D / KCHUNKS)

typedef unsigned long long u64;

// ---------------- scratch (device globals; no allocation allowed) -----------
__device__ float g_vm_partial[2][KCHUNKS][D]; // vecmat partials (reused twice)
__device__ float g_bw[2][D];                  // b_w per module
__device__ float g_main_partial[2][BPM][D];   // weighted-sum partials (UNnormalized)
__device__ float g_main_alpha[2][BPM];        // alpha-sum partials
__device__ float g_attn[2 * D];               // concat(res_in, res_out)

// packed f32x2 FMA: d = a*b + d   (SASS FFMA2; PTX-only form)
__device__ __forceinline__ void fma2(u64& d, u64 a, u64 b) {
    asm("fma.rn.f32x2 %0, %1, %2, %0;" : "+l"(d) : "l"(a), "l"(b));
}
__device__ __forceinline__ u64 pack2(float lo, float hi) {
    u64 r;
    asm("mov.b64 %0, {%1, %2};" : "=l"(r) : "f"(lo), "f"(hi));
    return r;
}
__device__ __forceinline__ void unpack2(float& lo, float& hi, u64 v) {
    asm("mov.b64 {%0, %1}, %2;" : "=f"(lo), "=f"(hi) : "l"(v));
}
// streaming 16B load (LDG.E.CS.128) — X has zero reuse
__device__ __forceinline__ void ldcs128(u64& a, u64& b, const void* p) {
    asm("ld.global.cs.v2.u64 {%0, %1}, [%2];" : "=l"(a), "=l"(b) : "l"(p));
}
// PDL primitives
__device__ __forceinline__ void gdc_wait() {
    asm volatile("griddepcontrol.wait;" ::: "memory");
}
__device__ __forceinline__ void gdc_launch() {
    asm volatile("griddepcontrol.launch_dependents;" ::: "memory");
}

// ---------------- stage-1 vecmat: b_w = b_alpha^T @ W_alpha ------------------
__global__ void vecmat_partial(const float* __restrict__ v0,
                               const float* __restrict__ M0,
                               const float* __restrict__ v1,
                               const float* __restrict__ M1) {
    int vec = blockIdx.y;
    const float* v = vec ? v1 : v0;
    const float4* M4 = (const float4*)(vec ? M1 : M0);
    int t = threadIdx.x;        // 0..255
    int k0 = blockIdx.x * KROWS;
    float4 acc = make_float4(0.f, 0.f, 0.f, 0.f);
#pragma unroll
    for (int kk = 0; kk < KROWS; kk++) {     // KROWS=16 fully unrolled -> MLP 16
        float vk = __ldg(v + k0 + kk);
        float4 m = M4[(size_t)(k0 + kk) * D4 + t];
        acc.x = fmaf(vk, m.x, acc.x);
        acc.y = fmaf(vk, m.y, acc.y);
        acc.z = fmaf(vk, m.z, acc.z);
        acc.w = fmaf(vk, m.w, acc.w);
    }
    ((float4*)g_vm_partial[vec][blockIdx.x])[t] = acc;
    gdc_launch();
}

// ---------------- reduce vm partials, split across 8 blocks/module ----------
// which==0 -> g_bw ; which==1 -> scale by 1/sum(alpha) -> g_attn
__global__ void vecmat_reduce(int which) {
    int vec = blockIdx.y;
    int t = threadIdx.x, grp = t >> 5, lane = t & 31;
    int c4 = blockIdx.x * 32 + lane;              // float4 column

    __shared__ float4 s_m[8][32];
    __shared__ float  s_inv;

    if (which && t < 32) {     // deterministic fixed-order alpha total
        float a = 0.f;
        for (int b = t; b < BPM; b += 32) a += g_main_alpha[vec][b];
#pragma unroll
        for (int o = 16; o > 0; o >>= 1)
            a += __shfl_xor_sync(0xffffffffu, a, o);
        if (t == 0) s_inv = 1.0f / a;
    }

    float4 acc = make_float4(0.f, 0.f, 0.f, 0.f);
#pragma unroll
    for (int c = grp; c < KCHUNKS; c += 8) {      // 8 chunks per thread
        float4 p = ((const float4*)g_vm_partial[vec][c])[c4];
        acc.x += p.x; acc.y += p.y; acc.z += p.z; acc.w += p.w;
    }
    s_m[grp][lane] = acc;
    __syncthreads();
    if (grp == 0) {
        float4 tot = s_m[0][lane];
#pragma unroll
        for (int w = 1; w < 8; w++) {
            float4 v = s_m[w][lane];
            tot.x += v.x; tot.y += v.y; tot.z += v.z; tot.w += v.w;
        }
        if (which) {
            float inv = s_inv;
            tot.x *= inv; tot.y *= inv; tot.z *= inv; tot.w *= inv;
            ((float4*)&g_attn[vec * D])[c4] = tot;
        } else {
            ((float4*)g_bw[vec])[c4] = tot;
        }
    }
    gdc_launch();
}

// ---------------- main single-pass kernel (body identical to R6) -------------
// warp-per-row: s = X_j . b_w ; alpha = exp(s) ; acc += alpha * X_j
__global__ void __launch_bounds__(256, 2)
main_pass(const float* __restrict__ Xin, const float* __restrict__ Xout, int nrows) {
    int mod = blockIdx.y;
    const ulonglong2* X2 = (const ulonglong2*)(mod ? Xout : Xin); // 16B units, 256/row

    __shared__ float4 s_red[8 * D4];
    __shared__ float  s_alpha[8];

    int t = threadIdx.x, warp = t >> 5, lane = t & 31;

    gdc_wait();    // PSS launch: wait for vecmat_reduce(0) before reading g_bw

    // b_w slice for this lane: float4 columns lane+32*i, i=0..7 -> 16 u64
    u64 bw[16];
    {
        const ulonglong2* B2 = (const ulonglong2*)g_bw[mod];
#pragma unroll
        for (int i = 0; i < 8; i++) {
            ulonglong2 v = B2[lane + 32 * i];
            bw[2 * i] = v.x; bw[2 * i + 1] = v.y;
        }
    }

    u64 acc[16];
#pragma unroll
    for (int i = 0; i < 16; i++) acc[i] = 0ull;
    float asum = 0.f;

    int gw = blockIdx.x * 8 + warp;
    const int NW = BPM * 8;

    for (int row = gw; row < nrows; row += NW) {
        const ulonglong2* xr = X2 + (size_t)row * 256;
        u64 r[16];
#pragma unroll
        for (int i = 0; i < 8; i++)               // 8 LDG.E.CS.128 front-batched
            ldcs128(r[2 * i], r[2 * i + 1], xr + lane + 32 * i);

        // dot: two independent f32x2 chains for ILP
        u64 d0 = 0ull, d1 = 0ull;
#pragma unroll
        for (int i = 0; i < 8; i++) {
            fma2(d0, r[2 * i],     bw[2 * i]);
            fma2(d1, r[2 * i + 1], bw[2 * i + 1]);
        }
        float a0, a1, b0, b1;
        unpack2(a0, a1, d0);
        unpack2(b0, b1, d1);
        float s = (a0 + a1) + (b0 + b1);
#pragma unroll
        for (int o = 16; o > 0; o >>= 1)
            s += __shfl_xor_sync(0xffffffffu, s, o);

        float alpha = __expf(s);                  // lane-uniform after butterfly
        asum += alpha;                            // per-lane asum == warp total
        u64 alpha2 = pack2(alpha, alpha);
#pragma unroll
        for (int i = 0; i < 16; i++) fma2(acc[i], alpha2, r[i]);
    }

    // deterministic block reduce: warp -> smem slot, fixed-order sum
#pragma unroll
    for (int i = 0; i < 8; i++) {
        float x, y, z, w;
        unpack2(x, y, acc[2 * i]);
        unpack2(z, w, acc[2 * i + 1]);
        s_red[warp * D4 + lane + 32 * i] = make_float4(x, y, z, w);
    }
    if (lane == 0) s_alpha[warp] = asum;          // asum already warp-total
    __syncthreads();

    float4 tot = make_float4(0.f, 0.f, 0.f, 0.f);
#pragma unroll
    for (int w = 0; w < 8; w++) {
        float4 v = s_red[w * D4 + t];
        tot.x += v.x; tot.y += v.y; tot.z += v.z; tot.w += v.w;
    }
    ((float4*)g_main_partial[mod][blockIdx.x])[t] = tot;
    if (t == 0) {
        float a = 0.f;
#pragma unroll
        for (int w = 0; w < 8; w++) a += s_alpha[w];
        g_main_alpha[mod][blockIdx.x] = a;
    }
    gdc_launch();
}

// ---------------- stage-2 vecmat, PDL: preload W_sum, then wait --------------
__global__ void vecmat_so_partial(const float* __restrict__ M0,
                                  const float* __restrict__ M1) {
    int vec = blockIdx.y;
    const float4* M4 = (const float4*)(vec ? M1 : M0);
    int t = threadIdx.x;
    int k0 = blockIdx.x * KROWS;

    // preload W_sum tile into registers — independent of main_pass (overlaps it)
    float4 m[KROWS];
#pragma unroll
    for (int kk = 0; kk < KROWS; kk++)
        m[kk] = M4[(size_t)(k0 + kk) * D4 + t];

    gdc_wait();    // now main_pass output is safe to read

    __shared__ float s_t[16][17];   // [rowgrp][col], padded
    __shared__ float s_v[KROWS];

    // COALESCED column reduce: consecutive threads -> consecutive columns
    {
        int g = t & 15, i = t >> 4;
        float a = 0.f;
        for (int b = i; b < BPM; b += 16)
            a += g_main_partial[vec][b][k0 + g];
        s_t[i][g] = a;
    }
    __syncthreads();
    if (t < KROWS) {                // 16 threads finish the 16-way sums
        float a = 0.f;
#pragma unroll
        for (int i = 0; i < 16; i++) a += s_t[i][t];
        s_v[t] = a;
    }
    __syncthreads();

    float4 acc = make_float4(0.f, 0.f, 0.f, 0.f);
#pragma unroll
    for (int kk = 0; kk < KROWS; kk++) {
        float vk = s_v[kk];
        acc.x = fmaf(vk, m[kk].x, acc.x);
        acc.y = fmaf(vk, m[kk].y, acc.y);
        acc.z = fmaf(vk, m[kk].z, acc.z);
        acc.w = fmaf(vk, m[kk].w, acc.w);
    }
    ((float4*)g_vm_partial[vec][blockIdx.x])[t] = acc;
    gdc_launch();
}

// ---------------- final, PDL: preload lin_W row, then wait for g_attn --------
__global__ void final_kernel(const float* __restrict__ linW,
                             const float* __restrict__ linb,
                             float* __restrict__ out) {
    int t = threadIdx.x;
    int i = blockIdx.x;

    // preload: independent of the attn chain (overlaps vso + vecmat_reduce(1))
    const float4* row = (const float4*)linW + (size_t)i * (2 * D4);
    float4 w1 = row[t];
    float4 w2 = row[t + D4];
    float  bias = linb[i];

    gdc_wait();    // g_attn now valid

    float4 a1 = ((const float4*)g_attn)[t];
    float4 a2 = ((const float4*)g_attn)[t + D4];
    float s = 0.f;
    s = fmaf(w1.x, a1.x, s); s = fmaf(w1.y, a1.y, s);
    s = fmaf(w1.z, a1.z, s); s = fmaf(w1.w, a1.w, s);
    s = fmaf(w2.x, a2.x, s); s = fmaf(w2.y, a2.y, s);
    s = fmaf(w2.z, a2.z, s); s = fmaf(w2.w, a2.w, s);

#pragma unroll
    for (int o = 16; o > 0; o >>= 1)
        s += __shfl_xor_sync(0xffffffffu, s, o);
    __shared__ float sw[8];
    int warp = t >> 5, lane = t & 31;
    if (lane == 0) sw[warp] = s;
    __syncthreads();
    if (t == 0) {
        float tot = 0.f;
#pragma unroll
        for (int w = 0; w < 8; w++) tot += sw[w];
        tot += bias;
        out[i] = tot > 0.f ? tot : expm1f(tot);   // jax.nn.elu, alpha=1
    }
}

// ---------------- PSS launch helper ------------------------------------------
static void launch_pss(const void* fn, dim3 grid, dim3 block, void** args) {
    cudaLaunchConfig_t cfg = {};
    cfg.gridDim = grid;
    cfg.blockDim = block;
    cfg.dynamicSmemBytes = 0;
    cfg.stream = 0;
    cudaLaunchAttribute at;
    at.id = cudaLaunchAttributeProgrammaticStreamSerialization;
    at.val.programmaticStreamSerializationAllowed = 1;
    cfg.attrs = &at;
    cfg.numAttrs = 1;
    cudaLaunchKernelExC(&cfg, fn, args);
}

// ---------------- launcher ---------------------------------------------------
extern "C" void kernel_launch(void* const* d_in, const int* in_sizes, int n_in,
                              void* d_out, int out_size) {
    const float* X_in      = (const float*)d_in[0];
    const float* X_out     = (const float*)d_in[1];
    const float* W_alpha_i = (const float*)d_in[2];
    // d_in[3] = a_alpha_in : unused (constant cancels in normalization)
    const float* b_alpha_i = (const float*)d_in[4];
    const float* W_sum_i   = (const float*)d_in[5];
    const float* W_alpha_o = (const float*)d_in[6];
    // d_in[7] = a_alpha_out : unused
    const float* b_alpha_o = (const float*)d_in[8];
    const float* W_sum_o   = (const float*)d_in[9];
    const float* lin_W     = (const float*)d_in[10];
    const float* lin_b     = (const float*)d_in[11];
    float* out = (float*)d_out;

    int nrows = in_sizes[0] / D;   // 50000

    // #1: b_w partials (normal launch)
    vecmat_partial<<<dim3(KCHUNKS, 2), 256>>>(b_alpha_i, W_alpha_i,
                                              b_alpha_o, W_alpha_o);
    // #2: reduce -> g_bw (normal)
    int which0 = 0, which1 = 1;
    vecmat_reduce<<<dim3(8, 2), 256>>>(which0);

    // #3: main pass (PSS: CTAs ramp during vecmat_reduce, wait before g_bw read)
    {
        const float* a = X_in; const float* b = X_out; int n = nrows;
        void* args[] = { (void*)&a, (void*)&b, (void*)&n };
        launch_pss((const void*)main_pass, dim3(BPM, 2), dim3(256), args);
    }

    // #4: fused column-reduce + GEMV vs W_sum (PSS: W_sum preload overlaps main_pass)
    {
        const float* a = W_sum_i; const float* b = W_sum_o;
        void* args[] = { (void*)&a, (void*)&b };
        launch_pss((const void*)vecmat_so_partial, dim3(KCHUNKS, 2), dim3(256), args);
    }

    // #5: reduce + scale by 1/sum(alpha) -> g_attn (normal)
    vecmat_reduce<<<dim3(8, 2), 256>>>(which1);

    // #6: final (PSS: lin_W preload overlaps vso + reduce)
    {
        const float* a = lin_W; const float* b = lin_b; float* o = out;
        void* args[] = { (void*)&a, (void*)&b, (void*)&o };
        launch_pss((const void*)final_kernel, dim3(D), dim3(256), args);
    }
}